// round 9
// baseline (speedup 1.0000x reference)
#include <cuda_runtime.h>
#include <cuda_fp16.h>
#include <stdint.h>
#include <math.h>

#define N_ROWS 65536
#define IN_DIM 768
#define OUT_DIM 256
#define NLEV 4
#define CB_SIZE 1024
#define FINF 3.4e38f

// ===================== scratch (device globals) ===============================
__device__ float g_mu[N_ROWS];
__device__ float g_rstd[N_ROWS];
__device__ float g_h1[(size_t)N_ROWS * OUT_DIM];
__device__ float g_res[(size_t)N_ROWS * OUT_DIM];
__device__ float g_qf[(size_t)N_ROWS * OUT_DIM];
__device__ float g_cnorm[NLEV * CB_SIZE];
__device__ int   g_cmax2[NLEV];
__device__ float g_rn2[N_ROWS];
// fp16 planes
__device__ __half g_resh[(size_t)N_ROWS * OUT_DIM];
__device__ __half g_qfh[(size_t)N_ROWS * OUT_DIM],  g_qfl[(size_t)N_ROWS * OUT_DIM];
__device__ __half g_hdh[(size_t)N_ROWS * IN_DIM],   g_hdl[(size_t)N_ROWS * IN_DIM];
// encoder weights: exact 3-way tf32 split (fp32-grade; feeds argmin)
__device__ float g_w1h[OUT_DIM * IN_DIM],  g_w1m[OUT_DIM * IN_DIM],  g_w1l[OUT_DIM * IN_DIM];
__device__ float g_w2h[OUT_DIM * OUT_DIM], g_w2m[OUT_DIM * OUT_DIM], g_w2l[OUT_DIM * OUT_DIM];
// decoder weights + codebooks: fp16 h plane only
__device__ __half g_wd1h[IN_DIM * OUT_DIM];
__device__ __half g_wd2h[IN_DIM * IN_DIM];
__device__ __half g_cbh[NLEV * CB_SIZE * OUT_DIM];
__device__ float4 g_part4[4 * N_ROWS];
__device__ double g_commit;
__device__ double g_rec;

// ===================== helpers ================================================
__device__ __forceinline__ float tf32r(float v) {
    uint32_t u;
    asm("cvt.rna.tf32.f32 %0, %1;" : "=r"(u) : "f"(v));
    return __uint_as_float(u);
}
__device__ __forceinline__ void split3(float v, float& h, float& m, float& l) {
    h = tf32r(v);
    float t = v - h;
    m = tf32r(t);
    l = t - m;
}
__device__ __forceinline__ void split2h(float v, __half& h, __half& l) {
    h = __float2half_rn(v);
    l = __float2half_rn(v - __half2float(h));
}
__device__ __forceinline__ uint32_t packh(__half a, __half b) {
    __half2 t = __halves2half2(a, b);
    return *reinterpret_cast<uint32_t*>(&t);
}
__device__ __forceinline__ uint32_t q4c(const uint4& q, int j) {
    return j == 0 ? q.x : j == 1 ? q.y : j == 2 ? q.z : q.w;
}
#define F2U(x) __float_as_uint(x)

#define MMA8(acc, a0, a1, a2, a3, bx, by) \
    asm volatile("mma.sync.aligned.m16n8k8.row.col.f32.tf32.tf32.f32 " \
        "{%0,%1,%2,%3}, {%4,%5,%6,%7}, {%8,%9}, {%0,%1,%2,%3};" \
        : "+f"((acc)[0]), "+f"((acc)[1]), "+f"((acc)[2]), "+f"((acc)[3]) \
        : "r"(a0), "r"(a1), "r"(a2), "r"(a3), "r"(bx), "r"(by))

#define MMA16(acc, a0, a1, a2, a3, bx, by) \
    asm volatile("mma.sync.aligned.m16n8k16.row.col.f32.f16.f16.f32 " \
        "{%0,%1,%2,%3}, {%4,%5,%6,%7}, {%8,%9}, {%0,%1,%2,%3};" \
        : "+f"((acc)[0]), "+f"((acc)[1]), "+f"((acc)[2]), "+f"((acc)[3]) \
        : "r"(a0), "r"(a1), "r"(a2), "r"(a3), "r"(bx), "r"(by))

// ===================== small kernels ==========================================
__global__ void ln_stats_kernel(const float* __restrict__ x) {
    if (blockIdx.x == 0 && threadIdx.x == 0) {
        g_commit = 0.0; g_rec = 0.0;
        for (int i = 0; i < NLEV; i++) g_cmax2[i] = 0;
    }
    int row = blockIdx.x;
    const float* xr = x + (size_t)row * IN_DIM;
    float s = 0.f, s2 = 0.f;
    for (int i = threadIdx.x; i < IN_DIM; i += 256) {
        float v = xr[i];
        s += v; s2 += v * v;
    }
    __shared__ float sh[16];
    #pragma unroll
    for (int o = 16; o; o >>= 1) {
        s  += __shfl_down_sync(0xffffffffu, s,  o);
        s2 += __shfl_down_sync(0xffffffffu, s2, o);
    }
    if ((threadIdx.x & 31) == 0) { sh[threadIdx.x >> 5] = s; sh[8 + (threadIdx.x >> 5)] = s2; }
    __syncthreads();
    if (threadIdx.x == 0) {
        float S = 0.f, S2 = 0.f;
        #pragma unroll
        for (int i = 0; i < 8; i++) { S += sh[i]; S2 += sh[8 + i]; }
        float mu = S / IN_DIM;
        float var = S2 / IN_DIM - mu * mu;
        g_mu[row] = mu;
        g_rstd[row] = rsqrtf(var + 1e-5f);
    }
}

__global__ void cnorm_kernel(const float* __restrict__ cb) {
    int code = blockIdx.x;
    float v = cb[(size_t)code * OUT_DIM + threadIdx.x];
    float s = v * v;
    __shared__ float sh[8];
    #pragma unroll
    for (int o = 16; o; o >>= 1) s += __shfl_down_sync(0xffffffffu, s, o);
    if ((threadIdx.x & 31) == 0) sh[threadIdx.x >> 5] = s;
    __syncthreads();
    if (threadIdx.x == 0) {
        float t = 0.f;
        #pragma unroll
        for (int i = 0; i < 8; i++) t += sh[i];
        g_cnorm[code] = t;
        atomicMax(&g_cmax2[blockIdx.x >> 10], __float_as_int(t));
    }
}

// one fused prep kernel: split3-T W1, W2; cvt-T Wd1, Wd2 (h only); cvt cb (h only)
__global__ void prep_kernel(const float* __restrict__ W1, const float* __restrict__ W2,
                            const float* __restrict__ Wd1, const float* __restrict__ Wd2,
                            const float* __restrict__ cbs) {
    int b = blockIdx.x, t = threadIdx.x;
    if (b < 768) {                       // W1 [768,256] -> [256,768] split3
        int i = b * 256 + t;
        int n = i / IN_DIM, k = i - n * IN_DIM;
        float h, m, l;
        split3(W1[(size_t)k * OUT_DIM + n], h, m, l);
        g_w1h[i] = h; g_w1m[i] = m; g_w1l[i] = l;
    } else if (b < 1024) {               // W2 [256,256] split3
        int i = (b - 768) * 256 + t;
        int n = i / OUT_DIM, k = i - n * OUT_DIM;
        float h, m, l;
        split3(W2[(size_t)k * OUT_DIM + n], h, m, l);
        g_w2h[i] = h; g_w2m[i] = m; g_w2l[i] = l;
    } else if (b < 1792) {               // Wd1 [256,768] -> [768,256] cvt h
        int i = (b - 1024) * 256 + t;
        int n = i / OUT_DIM, k = i - n * OUT_DIM;
        g_wd1h[i] = __float2half_rn(Wd1[(size_t)k * IN_DIM + n]);
    } else if (b < 4096) {               // Wd2 [768,768] cvt h
        int i = (b - 1792) * 256 + t;
        int n = i / IN_DIM, k = i - n * IN_DIM;
        g_wd2h[i] = __float2half_rn(Wd2[(size_t)k * IN_DIM + n]);
    } else {                             // codebooks cvt h
        int i = (b - 4096) * 256 + t;
        g_cbh[i] = __float2half_rn(cbs[i]);
    }
}

__global__ void sum_rn2_kernel() {
    int i = (blockIdx.x * 256 + threadIdx.x) * 4;
    float4 v = *(const float4*)(g_rn2 + i);
    float s = v.x + v.y + v.z + v.w;
    __shared__ float sh[8];
    #pragma unroll
    for (int o = 16; o; o >>= 1) s += __shfl_down_sync(0xffffffffu, s, o);
    if ((threadIdx.x & 31) == 0) sh[threadIdx.x >> 5] = s;
    __syncthreads();
    if (threadIdx.x == 0) {
        float t = 0.f;
        #pragma unroll
        for (int i2 = 0; i2 < 8; i2++) t += sh[i2];
        atomicAdd(&g_commit, (double)t);
    }
}

__global__ void final_kernel(float* __restrict__ out) {
    double rec = g_rec / ((double)N_ROWS * (double)IN_DIM);
    double com = g_commit / ((double)N_ROWS * (double)OUT_DIM);
    out[0] = (float)(rec + 0.25 * com);
}

// ======= fused RQ step: resolve partials + (conditional exact rescreen) + update
__global__ void __launch_bounds__(256)
rq_step_kernel(const float* __restrict__ cb, const float* __restrict__ cn,
               float* __restrict__ out_idx, int level) {
    __shared__ float sr[256];
    __shared__ int s_idx;
    __shared__ float s_red[8];
    __shared__ float2 sw[8];
    const int row = blockIdx.x;
    const int tid = threadIdx.x;
    const int wid = tid >> 5, lane = tid & 31;

    if (tid == 0) {
        float d1 = FINF, d2 = FINF;
        int i1 = 0;
        #pragma unroll
        for (int nt = 0; nt < 4; nt++) {
            float4 p = g_part4[(size_t)nt * N_ROWS + row];
            int pi = (int)p.y;
            if (p.x < d1 || (p.x == d1 && pi < i1)) {
                d2 = fminf(d1, p.z);
                d1 = p.x; i1 = pi;
            } else {
                d2 = fminf(d2, p.x);
            }
        }
        float cm2 = __int_as_float(g_cmax2[level]);
        float E = 3e-4f * sqrtf(g_rn2[row] * cm2);
        s_idx = (d2 - d1 <= E) ? -1 : i1;   // -1 => ambiguous, exact rescreen
    }
    sr[tid] = g_res[(size_t)row * 256 + tid];
    __syncthreads();
    int idx = s_idx;

    if (idx < 0) {
        const float4* rp = (const float4*)(sr + lane * 8);
        float4 r0 = rp[0], r1 = rp[1];
        float bd = FINF; int bi = 0;
        for (int j = 0; j < 128; j++) {
            int c = wid * 128 + j;
            const float4* cp = (const float4*)(cb + (size_t)c * 256 + lane * 8);
            float4 v0 = cp[0], v1 = cp[1];
            float s = v0.x*r0.x + v0.y*r0.y + v0.z*r0.z + v0.w*r0.w
                    + v1.x*r1.x + v1.y*r1.y + v1.z*r1.z + v1.w*r1.w;
            #pragma unroll
            for (int o = 16; o; o >>= 1) s += __shfl_xor_sync(0xffffffffu, s, o);
            float d = cn[c] - 2.f * s;
            if (d < bd) { bd = d; bi = c; }
        }
        if (lane == 0) sw[wid] = make_float2(bd, (float)bi);
        __syncthreads();
        if (tid == 0) {
            float d1 = FINF; int i1 = 0;
            #pragma unroll
            for (int w = 0; w < 8; w++) {
                int wi = (int)sw[w].y;
                if (sw[w].x < d1 || (sw[w].x == d1 && wi < i1)) { d1 = sw[w].x; i1 = wi; }
            }
            s_idx = i1;
        }
        __syncthreads();
        idx = s_idx;
    }

    if (tid == 0) out_idx[(size_t)row * 4 + level] = (float)idx;

    // update: residual, h plane, qf, rn2 (commit summed by sum_rn2_kernel)
    size_t off = (size_t)row * 256 + tid;
    float r = sr[tid];
    float q = cb[(size_t)idx * 256 + tid];
    float d = r - q;
    g_res[off] = d;
    g_resh[off] = __float2half_rn(d);
    float qv = (level == 0) ? q : (g_qf[off] + q);
    g_qf[off] = qv;
    if (level == NLEV - 1) {
        __half qh, ql;
        split2h(qv, qh, ql);
        g_qfh[off] = qh; g_qfl[off] = ql;
    }
    float cs = d * d;
    #pragma unroll
    for (int o = 16; o; o >>= 1) cs += __shfl_down_sync(0xffffffffu, cs, o);
    if ((tid & 31) == 0) s_red[tid >> 5] = cs;
    __syncthreads();
    if (tid == 0) {
        float t = 0.f;
        #pragma unroll
        for (int i = 0; i < 8; i++) t += s_red[i];
        g_rn2[row] = t;
    }
}

// ===================== tf32 exact 6-term GEMM, BK=8 double-buffered ==========
// Block 128x256, 8 warps (2M x 4N), warp 64x64. One k8-step per chunk.
// Stage: A 3 planes x [128][12], B 3 planes x [256][12]; pair (c, c+4) at 2c.
// Pipeline: prefetch LDG(c+1) -> MMA(c) -> STS(c+1 -> other stage) -> sync.
// EPI: 1 bias+relu store; 4 bias store + resh fp16 plane + per-row rn2 (enc2).
#define ASTR2 12
#define T_SZA (128 * ASTR2)
#define T_SZB (256 * ASTR2)
#define T_OB  (3 * T_SZA)
#define T_STGF (3 * T_SZA + 3 * T_SZB)      // 13824 floats
#define SMEM_TF (2 * T_STGF * 4)            // 110592 bytes

template <int AOP, int EPI>
__global__ void __launch_bounds__(256, 1)
gemm_mma(const float* __restrict__ A,
         const float* __restrict__ B0, const float* __restrict__ B1,
         const float* __restrict__ B2,
         const float* __restrict__ bias, float* __restrict__ C,
         int K, int Nn,
         const float* __restrict__ lng, const float* __restrict__ lnb)
{
    extern __shared__ float sm[];

    const int tid = threadIdx.x;
    const int lane = tid & 31;
    const int wid = tid >> 5;
    const int wm = wid >> 2;
    const int wn = wid & 3;
    const int r = lane >> 2;
    const int cq = lane & 3;
    const int m0 = blockIdx.y * 128;
    const int n0 = blockIdx.x * 256;

    // staging roles: A row split across 2 threads (4 k each); B full row per thread
    const int arow = tid >> 1;
    const int ahalf = tid & 1;          // 0: k 0..3 (pair lows), 1: k 4..7 (highs)
    const int gma = m0 + arow;
    float mu = 0.f, rstd = 0.f;
    if (AOP == 1) { mu = g_mu[gma]; rstd = g_rstd[gma]; }
    const int rotA = (arow + (arow >> 2)) & 3;
    const int brow = tid;
    const int rotB = (brow + (brow >> 2)) & 3;
    const float* Bp[3] = {B0, B1, B2};

    float acc[4][8][4];
    #pragma unroll
    for (int mt = 0; mt < 4; mt++)
        #pragma unroll
        for (int nt = 0; nt < 8; nt++)
            #pragma unroll
            for (int q = 0; q < 4; q++) acc[mt][nt][q] = 0.f;

    const int NC = K >> 3;
    float4 afr;          // A prefetch: k = ahalf*4 .. +3
    float4 bfr[3][2];    // B prefetch: 3 planes x 8 floats

    auto prefetch = [&](int c) {
        const int k0 = c * 8;
        afr = *(const float4*)(A + (size_t)gma * K + k0 + ahalf * 4);
        #pragma unroll
        for (int s = 0; s < 3; s++) {
            const float* src = Bp[s] + (size_t)(n0 + brow) * K + k0;
            bfr[s][0] = *(const float4*)(src);
            bfr[s][1] = *(const float4*)(src + 4);
        }
    };
    auto store_stage = [&](int stg, int c) {
        float* st = sm + stg * T_STGF;
        const int k0 = c * 8;
        // ---- A: split3 the 4 owned values, scatter into 3 planes ----
        {
            float v[4] = {afr.x, afr.y, afr.z, afr.w};
            if (AOP == 1) {
                float4 g4 = *(const float4*)(lng + k0 + ahalf * 4);
                float4 b4 = *(const float4*)(lnb + k0 + ahalf * 4);
                v[0] = (v[0] - mu) * rstd * g4.x + b4.x;
                v[1] = (v[1] - mu) * rstd * g4.y + b4.y;
                v[2] = (v[2] - mu) * rstd * g4.z + b4.z;
                v[3] = (v[3] - mu) * rstd * g4.w + b4.w;
            }
            float vs[3][4];
            #pragma unroll
            for (int e = 0; e < 4; e++)
                split3(v[e], vs[0][e], vs[1][e], vs[2][e]);
            #pragma unroll
            for (int s = 0; s < 3; s++) {
                float* bS = st + s * T_SZA + arow * ASTR2;
                #pragma unroll
                for (int j = 0; j < 4; j++) {
                    int cc = (j + rotA) & 3;
                    bS[2 * cc + ahalf] = vs[s][cc];
                }
            }
        }
        // ---- B: pure copy from pre-split gmem planes ----
        #pragma unroll
        for (int s = 0; s < 3; s++) {
            float v[8] = {bfr[s][0].x, bfr[s][0].y, bfr[s][0].z, bfr[s][0].w,
                          bfr[s][1].x, bfr[s][1].y, bfr[s][1].z, bfr[s][1].w};
            float* bS = st + T_OB + s * T_SZB + brow * ASTR2;
            #pragma unroll
            for (int j = 0; j < 4; j++) {
                int cc = (j + rotB) & 3;
                *(float2*)&bS[2 * cc] = make_float2(v[cc], v[cc + 4]);
            }
        }
    };

    prefetch(0);
    store_stage(0, 0);
    __syncthreads();

    for (int c = 0; c < NC; c++) {
        if (c + 1 < NC) prefetch(c + 1);

        const float* st = sm + (c & 1) * T_STGF;
        float2 fb[3][8];
        #pragma unroll
        for (int s = 0; s < 3; s++)
            #pragma unroll
            for (int nt = 0; nt < 8; nt++) {
                int n = wn * 64 + nt * 8 + r;
                fb[s][nt] = *(const float2*)&st[T_OB + s * T_SZB + n * ASTR2 + 2 * cq];
            }
        #pragma unroll
        for (int mt = 0; mt < 4; mt++) {
            int mrow = wm * 64 + mt * 16 + r;
            int offa = mrow * ASTR2 + 2 * cq;
            float2 a0[3], a1[3];
            #pragma unroll
            for (int s = 0; s < 3; s++) {
                a0[s] = *(const float2*)&st[s * T_SZA + offa];
                a1[s] = *(const float2*)&st[s * T_SZA + offa + 8 * ASTR2];
            }
            const int TA[6] = {0, 0, 1, 0, 2, 1};
            const int TB[6] = {0, 1, 0, 2, 0, 1};
            #pragma unroll
            for (int t = 0; t < 6; t++) {
                int sa = TA[t], sb = TB[t];
                uint32_t A0 = F2U(a0[sa].x), A1 = F2U(a1[sa].x);
                uint32_t A2 = F2U(a0[sa].y), A3 = F2U(a1[sa].y);
                #pragma unroll
                for (int nt = 0; nt < 8; nt++)
                    MMA8(acc[mt][nt], A0, A1, A2, A3,
                         F2U(fb[sb][nt].x), F2U(fb[sb][nt].y));
            }
        }

        if (c + 1 < NC) store_stage((c + 1) & 1, c + 1);
        __syncthreads();
    }

    if (EPI != 4) {
        #pragma unroll
        for (int mt = 0; mt < 4; mt++) {
            int row = m0 + wm * 64 + mt * 16 + r;
            #pragma unroll
            for (int nt = 0; nt < 8; nt++) {
                int col = n0 + wn * 64 + nt * 8 + 2 * cq;
                float2 bb = *(const float2*)(bias + col);
                float o0 = acc[mt][nt][0] + bb.x, o1 = acc[mt][nt][1] + bb.y;
                float o2 = acc[mt][nt][2] + bb.x, o3 = acc[mt][nt][3] + bb.y;
                if (EPI == 1) {
                    o0 = fmaxf(o0, 0.f); o1 = fmaxf(o1, 0.f);
                    o2 = fmaxf(o2, 0.f); o3 = fmaxf(o3, 0.f);
                }
                *(float2*)(C + (size_t)row * Nn + col) = make_float2(o0, o1);
                *(float2*)(C + (size_t)(row + 8) * Nn + col) = make_float2(o2, o3);
            }
        }
    } else {
        // EPI 4 (enc2): res fp32 + resh fp16 plane + per-row rn2
        float lsr[4][2];
        #pragma unroll
        for (int mt = 0; mt < 4; mt++) { lsr[mt][0] = 0.f; lsr[mt][1] = 0.f; }
        #pragma unroll
        for (int mt = 0; mt < 4; mt++) {
            int row = m0 + wm * 64 + mt * 16 + r;
            #pragma unroll
            for (int nt = 0; nt < 8; nt++) {
                int col = n0 + wn * 64 + nt * 8 + 2 * cq;
                float2 bb = *(const float2*)(bias + col);
                float o0 = acc[mt][nt][0] + bb.x, o1 = acc[mt][nt][1] + bb.y;
                float o2 = acc[mt][nt][2] + bb.x, o3 = acc[mt][nt][3] + bb.y;
                *(float2*)(C + (size_t)row * Nn + col) = make_float2(o0, o1);
                *(float2*)(C + (size_t)(row + 8) * Nn + col) = make_float2(o2, o3);
                *(uint32_t*)(g_resh + (size_t)row * Nn + col) =
                    packh(__float2half_rn(o0), __float2half_rn(o1));
                *(uint32_t*)(g_resh + (size_t)(row + 8) * Nn + col) =
                    packh(__float2half_rn(o2), __float2half_rn(o3));
                lsr[mt][0] = fmaf(o0, o0, fmaf(o1, o1, lsr[mt][0]));
                lsr[mt][1] = fmaf(o2, o2, fmaf(o3, o3, lsr[mt][1]));
            }
        }
        __syncthreads();
        float* sred = sm;   // [128][4]
        #pragma unroll
        for (int mt = 0; mt < 4; mt++) {
            float s0 = lsr[mt][0], s1 = lsr[mt][1];
            s0 += __shfl_xor_sync(0xffffffffu, s0, 1);
            s0 += __shfl_xor_sync(0xffffffffu, s0, 2);
            s1 += __shfl_xor_sync(0xffffffffu, s1, 1);
            s1 += __shfl_xor_sync(0xffffffffu, s1, 2);
            if (cq == 0) {
                int lr = wm * 64 + mt * 16 + r;
                sred[lr * 4 + wn] = s0;
                sred[(lr + 8) * 4 + wn] = s1;
            }
        }
        __syncthreads();
        if (tid < 128)
            g_rn2[m0 + tid] = sred[tid * 4] + sred[tid * 4 + 1]
                            + sred[tid * 4 + 2] + sred[tid * 4 + 3];
    }
}

// ===================== fp16 k16 NTERM GEMM, presplit operands =================
template <int EPI, int NTERM>
__global__ void __launch_bounds__(256, 1)
gemm_h(const __half* __restrict__ A0, const __half* __restrict__ A1,
       const __half* __restrict__ B0,
       const float* __restrict__ bias, float* __restrict__ C,
       __half* __restrict__ C0, __half* __restrict__ C1,
       int K, int Nn,
       const float* __restrict__ xref, float4* __restrict__ part)
{
    constexpr int PA = (NTERM >= 2) ? 2 : 1;
    constexpr int APL = 2048;
    constexpr int BPL = 4096;
    constexpr int BBASE = PA * 2 * APL;
    constexpr int STG = PA * 2 * APL + 2 * BPL;

    extern __shared__ __half smh[];
    const int tid = threadIdx.x;
    const int lane = tid & 31;
    const int wid = tid >> 5;
    const int wm = wid >> 2;
    const int wn = wid & 3;
    const int r = lane >> 2;
    const int cq = lane & 3;
    const int m0 = blockIdx.y * 128;
    const int n0 = blockIdx.x * 256;

    const int srow = tid >> 1;
    const int sb   = tid & 1;
    const __half* Ap[2] = {A0, A1};

    float acc[4][8][4];
    #pragma unroll
    for (int mt = 0; mt < 4; mt++)
        #pragma unroll
        for (int nt = 0; nt < 8; nt++)
            #pragma unroll
            for (int q = 0; q < 4; q++) acc[mt][nt][q] = 0.f;

    const int NC = K >> 5;
    uint4 af[PA][2];
    uint4 bf[4];

    auto load_regs = [&](int c) {
        #pragma unroll
        for (int s = 0; s < PA; s++) {
            const uint4* ap = (const uint4*)(Ap[s] + (size_t)(m0 + srow) * K + c * 32 + sb * 16);
            af[s][0] = ap[0];
            af[s][1] = ap[1];
        }
        const uint4* bp = (const uint4*)(B0 + (size_t)(n0 + tid) * K + c * 32);
        bf[0] = bp[0]; bf[1] = bp[1]; bf[2] = bp[2]; bf[3] = bp[3];
    };
    auto store_stage = [&](int stg) {
        __half* st = smh + stg * STG;
        #pragma unroll
        for (int s = 0; s < PA; s++) {
            __half* base = st + (s * 2 + sb) * APL + srow * 16;
            #pragma unroll
            for (int j = 0; j < 4; j++) {
                int jj = (j + 2 * sb) & 3;
                int ps = (jj + (srow >> 2)) & 3;
                uint2 val;
                val.x = q4c(af[s][0], jj);
                val.y = q4c(af[s][1], jj);
                *(uint2*)(base + ps * 4) = val;
            }
        }
        #pragma unroll
        for (int b = 0; b < 2; b++) {
            __half* bbase = st + BBASE + b * BPL + tid * 16;
            #pragma unroll
            for (int j = 0; j < 4; j++) {
                int jj = (j + 2 * b) & 3;
                int ps = (jj + (tid >> 2)) & 3;
                uint2 val;
                val.x = q4c(bf[2 * b], jj);
                val.y = q4c(bf[2 * b + 1], jj);
                *(uint2*)(bbase + ps * 4) = val;
            }
        }
    };

    load_regs(0);
    store_stage(0);
    __syncthreads();

    for (int c = 0; c < NC; c++) {
        if (c + 1 < NC) load_regs(c + 1);

        const __half* st = smh + (c & 1) * STG;
        #pragma unroll
        for (int b = 0; b < 2; b++) {
            uint2 fbr[8];
            #pragma unroll
            for (int nt = 0; nt < 8; nt++) {
                int n = wn * 64 + nt * 8 + r;
                int ps = (cq + (n >> 2)) & 3;
                fbr[nt] = *(const uint2*)(st + BBASE + b * BPL + n * 16 + ps * 4);
            }
            #pragma unroll
            for (int mt = 0; mt < 4; mt++) {
                int row = wm * 64 + mt * 16 + r;
                int ps  = (cq + (row >> 2)) & 3;
                int ps8 = (cq + (row >> 2) + 2) & 3;
                uint2 ua[PA], va[PA];
                #pragma unroll
                for (int s = 0; s < PA; s++) {
                    ua[s] = *(const uint2*)(st + (s * 2 + b) * APL + row * 16 + ps * 4);
                    va[s] = *(const uint2*)(st + (s * 2 + b) * APL + (row + 8) * 16 + ps8 * 4);
                }
                #pragma unroll
                for (int t = 0; t < NTERM; t++) {
                    #pragma unroll
                    for (int nt = 0; nt < 8; nt++)
                        MMA16(acc[mt][nt], ua[t].x, va[t].x, ua[t].y, va[t].y,
                              fbr[nt].x, fbr[nt].y);
                }
            }
        }

        if (c + 1 < NC) store_stage((c + 1) & 1);
        __syncthreads();
    }

    // =================== epilogue ===================
    if (EPI == 1) {
        #pragma unroll
        for (int mt = 0; mt < 4; mt++) {
            int row = m0 + wm * 64 + mt * 16 + r;
            #pragma unroll
            for (int nt = 0; nt < 8; nt++) {
                int col = n0 + wn * 64 + nt * 8 + 2 * cq;
                float2 bb = *(const float2*)(bias + col);
                float o0 = fmaxf(acc[mt][nt][0] + bb.x, 0.f);
                float o1 = fmaxf(acc[mt][nt][1] + bb.y, 0.f);
                float o2 = fmaxf(acc[mt][nt][2] + bb.x, 0.f);
                float o3 = fmaxf(acc[mt][nt][3] + bb.y, 0.f);
                __half h0, l0, h1, l1, h2, l2, h3, l3;
                split2h(o0, h0, l0); split2h(o1, h1, l1);
                split2h(o2, h2, l2); split2h(o3, h3, l3);
                *(uint32_t*)(C0 + (size_t)row * Nn + col) = packh(h0, h1);
                *(uint32_t*)(C1 + (size_t)row * Nn + col) = packh(l0, l1);
                *(uint32_t*)(C0 + (size_t)(row + 8) * Nn + col) = packh(h2, h3);
                *(uint32_t*)(C1 + (size_t)(row + 8) * Nn + col) = packh(l2, l3);
            }
        }
    } else if (EPI == 2) {
        float lsum = 0.f;
        #pragma unroll
        for (int mt = 0; mt < 4; mt++) {
            int row = m0 + wm * 64 + mt * 16 + r;
            #pragma unroll
            for (int nt = 0; nt < 8; nt++) {
                int col = n0 + wn * 64 + nt * 8 + 2 * cq;
                float2 bb = *(const float2*)(bias + col);
                float2 x0 = *(const float2*)(xref + (size_t)row * Nn + col);
                float2 x1 = *(const float2*)(xref + (size_t)(row + 8) * Nn + col);
                float o0 = acc[mt][nt][0] + bb.x, o1 = acc[mt][nt][1] + bb.y;
                float o2 = acc[mt][nt][2] + bb.x, o3 = acc[mt][nt][3] + bb.y;
                float d0 = o0 - x0.x, d1 = o1 - x0.y, d2 = o2 - x1.x, d3 = o3 - x1.y;
                lsum = fmaf(d0, d0, lsum); lsum = fmaf(d1, d1, lsum);
                lsum = fmaf(d2, d2, lsum); lsum = fmaf(d3, d3, lsum);
                float* c0 = C + (size_t)row * Nn + col;        // 4B-aligned only
                float* c1 = C + (size_t)(row + 8) * Nn + col;
                c0[0] = o0; c0[1] = o1; c1[0] = o2; c1[1] = o3;
            }
        }
        #pragma unroll
        for (int o = 16; o; o >>= 1) lsum += __shfl_down_sync(0xffffffffu, lsum, o);
        if (lane == 0) atomicAdd(&g_rec, (double)lsum);
    } else {  // EPI 3: top-2 distance partial (bias = cnorm)
        __syncthreads();
        float4* sred = (float4*)smh;
        #pragma unroll
        for (int mt = 0; mt < 4; mt++) {
            float bd[2] = {FINF, FINF}, b2[2] = {FINF, FINF};
            int bi[2] = {0, 0};
            #pragma unroll
            for (int nt = 0; nt < 8; nt++) {
                int col = n0 + wn * 64 + nt * 8 + 2 * cq;
                float2 cn = *(const float2*)(bias + col);
                float dv[4];
                dv[0] = cn.x - 2.f * acc[mt][nt][0];
                dv[1] = cn.y - 2.f * acc[mt][nt][1];
                dv[2] = cn.x - 2.f * acc[mt][nt][2];
                dv[3] = cn.y - 2.f * acc[mt][nt][3];
                #pragma unroll
                for (int e = 0; e < 4; e++) {
                    int slot = e >> 1;
                    int ci = col + (e & 1);
                    if (dv[e] < bd[slot]) { b2[slot] = bd[slot]; bd[slot] = dv[e]; bi[slot] = ci; }
                    else b2[slot] = fminf(b2[slot], dv[e]);
                }
            }
            #pragma unroll
            for (int off = 1; off <= 2; off <<= 1) {
                #pragma unroll
                for (int slot = 0; slot < 2; slot++) {
                    float od = __shfl_xor_sync(0xffffffffu, bd[slot], off);
                    int   oi = __shfl_xor_sync(0xffffffffu, bi[slot], off);
                    float o2 = __shfl_xor_sync(0xffffffffu, b2[slot], off);
                    if (od < bd[slot] || (od == bd[slot] && oi < bi[slot])) {
                        b2[slot] = fminf(bd[slot], o2);
                        bd[slot] = od; bi[slot] = oi;
                    } else {
                        b2[slot] = fminf(b2[slot], od);
                    }
                }
            }
            if (cq == 0) {
                int lr = wm * 64 + mt * 16 + r;
                sred[lr * 4 + wn] = make_float4(bd[0], (float)bi[0], b2[0], 0.f);
                sred[(lr + 8) * 4 + wn] = make_float4(bd[1], (float)bi[1], b2[1], 0.f);
            }
        }
        __syncthreads();
        if (tid < 128) {
            float d1 = FINF, d2 = FINF;
            int i1 = 0;
            #pragma unroll
            for (int w = 0; w < 4; w++) {
                float4 p = sred[tid * 4 + w];
                int pi = (int)p.y;
                if (p.x < d1 || (p.x == d1 && pi < i1)) {
                    d2 = fminf(d1, p.z);
                    d1 = p.x; i1 = pi;
                } else {
                    d2 = fminf(d2, p.x);
                }
            }
            part[(size_t)blockIdx.x * N_ROWS + m0 + tid] =
                make_float4(d1, (float)i1, d2, 0.f);
        }
    }
}

// ===================== launch ==================================================
extern "C" void kernel_launch(void* const* d_in, const int* in_sizes, int n_in,
                              void* d_out, int out_size)
{
    (void)in_sizes; (void)n_in; (void)out_size;
    const float* x    = (const float*)d_in[0];
    const float* ln_g = (const float*)d_in[1];
    const float* ln_b = (const float*)d_in[2];
    const float* W1   = (const float*)d_in[3];
    const float* b1   = (const float*)d_in[4];
    const float* W2   = (const float*)d_in[5];
    const float* b2   = (const float*)d_in[6];
    const float* Wd1  = (const float*)d_in[7];
    const float* bd1  = (const float*)d_in[8];
    const float* Wd2  = (const float*)d_in[9];
    const float* bd2  = (const float*)d_in[10];
    const float* cbs  = (const float*)d_in[11];

    float* out   = (float*)d_out;
    float* recon = out + 1;
    float* oidx  = out + 1 + (size_t)N_ROWS * IN_DIM;

    void* p;
    cudaGetSymbolAddress(&p, g_h1);    float* h1    = (float*)p;
    cudaGetSymbolAddress(&p, g_res);   float* res   = (float*)p;
    cudaGetSymbolAddress(&p, g_cnorm); float* cnrm  = (float*)p;
    cudaGetSymbolAddress(&p, g_resh);  __half* resh = (__half*)p;
    cudaGetSymbolAddress(&p, g_qfh);   __half* qfh  = (__half*)p;
    cudaGetSymbolAddress(&p, g_qfl);   __half* qfl  = (__half*)p;
    cudaGetSymbolAddress(&p, g_hdh);   __half* hdh  = (__half*)p;
    cudaGetSymbolAddress(&p, g_hdl);   __half* hdl  = (__half*)p;
    cudaGetSymbolAddress(&p, g_w1h);   float* w1h   = (float*)p;
    cudaGetSymbolAddress(&p, g_w1m);   float* w1m   = (float*)p;
    cudaGetSymbolAddress(&p, g_w1l);   float* w1l   = (float*)p;
    cudaGetSymbolAddress(&p, g_w2h);   float* w2h   = (float*)p;
    cudaGetSymbolAddress(&p, g_w2m);   float* w2m   = (float*)p;
    cudaGetSymbolAddress(&p, g_w2l);   float* w2l   = (float*)p;
    cudaGetSymbolAddress(&p, g_wd1h);  __half* wd1h = (__half*)p;
    cudaGetSymbolAddress(&p, g_wd2h);  __half* wd2h = (__half*)p;
    cudaGetSymbolAddress(&p, g_cbh);   __half* cbh  = (__half*)p;
    cudaGetSymbolAddress(&p, g_part4); float4* part = (float4*)p;

    const int HS1 = 2 * (1 * 4096 + 8192) * 2;        // NTERM=1: 49152
    const int HS2 = 2 * (2 * 4096 + 8192) * 2;        // NTERM=2: 65536
    cudaFuncSetAttribute(gemm_mma<1, 1>, cudaFuncAttributeMaxDynamicSharedMemorySize, SMEM_TF);
    cudaFuncSetAttribute(gemm_mma<0, 4>, cudaFuncAttributeMaxDynamicSharedMemorySize, SMEM_TF);
    cudaFuncSetAttribute(gemm_h<3, 1>, cudaFuncAttributeMaxDynamicSharedMemorySize, HS1);
    cudaFuncSetAttribute(gemm_h<1, 2>, cudaFuncAttributeMaxDynamicSharedMemorySize, HS2);
    cudaFuncSetAttribute(gemm_h<2, 2>, cudaFuncAttributeMaxDynamicSharedMemorySize, HS2);

    prep_kernel<<<8192, 256>>>(W1, W2, Wd1, Wd2, cbs);
    ln_stats_kernel<<<N_ROWS, 256>>>(x);
    gemm_mma<1, 1><<<dim3(1, N_ROWS / 128), 256, SMEM_TF>>>(
        x, w1h, w1m, w1l, b1, h1, IN_DIM, OUT_DIM, ln_g, ln_b);
    gemm_mma<0, 4><<<dim3(1, N_ROWS / 128), 256, SMEM_TF>>>(
        h1, w2h, w2m, w2l, b2, res, OUT_DIM, OUT_DIM, nullptr, nullptr);
    cnorm_kernel<<<NLEV * CB_SIZE, 256>>>(cbs);

    // residual quantization: 1-term fp16 prescreen + margin-certified rescreen
    for (int l = 0; l < NLEV; l++) {
        gemm_h<3, 1><<<dim3(4, N_ROWS / 128), 256, HS1>>>(
            resh, nullptr, cbh + (size_t)l * CB_SIZE * OUT_DIM,
            cnrm + l * CB_SIZE, nullptr, nullptr, nullptr,
            OUT_DIM, CB_SIZE, nullptr, part);
        rq_step_kernel<<<N_ROWS, 256>>>(cbs + (size_t)l * CB_SIZE * OUT_DIM,
                                        cnrm + l * CB_SIZE, oidx, l);
        sum_rn2_kernel<<<64, 256>>>();
    }

    // decoder (2-term: exact-A x fp16-B)
    gemm_h<1, 2><<<dim3(3, N_ROWS / 128), 256, HS2>>>(
        qfh, qfl, wd1h, bd1, nullptr, hdh, hdl,
        OUT_DIM, IN_DIM, nullptr, nullptr);
    gemm_h<2, 2><<<dim3(3, N_ROWS / 128), 256, HS2>>>(
        hdh, hdl, wd2h, bd2, recon, nullptr, nullptr,
        IN_DIM, IN_DIM, x, nullptr);

    final_kernel<<<1, 1>>>(out);
}

// round 10
// speedup vs baseline: 1.3406x; 1.3406x over previous
#include <cuda_runtime.h>
#include <cuda_fp16.h>
#include <cuda_bf16.h>
#include <stdint.h>
#include <math.h>

#define N_ROWS 65536
#define IN_DIM 768
#define OUT_DIM 256
#define NLEV 4
#define CB_SIZE 1024
#define FINF 3.4e38f

typedef __nv_bfloat16 bf16;

// ===================== scratch (device globals) ===============================
__device__ float g_h1_unused[1];
__device__ float g_res[(size_t)N_ROWS * OUT_DIM];
__device__ float g_qf[(size_t)N_ROWS * OUT_DIM];
__device__ float g_cnorm[NLEV * CB_SIZE];
__device__ int   g_cmax2[NLEV];
__device__ float g_rn2[N_ROWS];
// fp16 planes
__device__ __half g_resh[(size_t)N_ROWS * OUT_DIM];
__device__ __half g_qfh[(size_t)N_ROWS * OUT_DIM],  g_qfl[(size_t)N_ROWS * OUT_DIM];
__device__ __half g_hdh[(size_t)N_ROWS * IN_DIM],   g_hdl[(size_t)N_ROWS * IN_DIM];
// bf16 3-plane splits (encoder path, fp32-grade)
__device__ bf16 g_xn0[(size_t)N_ROWS * IN_DIM], g_xn1[(size_t)N_ROWS * IN_DIM],
                g_xn2[(size_t)N_ROWS * IN_DIM];
__device__ bf16 g_h1b0[(size_t)N_ROWS * OUT_DIM], g_h1b1[(size_t)N_ROWS * OUT_DIM],
                g_h1b2[(size_t)N_ROWS * OUT_DIM];
__device__ bf16 g_w1b0[OUT_DIM * IN_DIM], g_w1b1[OUT_DIM * IN_DIM], g_w1b2[OUT_DIM * IN_DIM];
__device__ bf16 g_w2b0[OUT_DIM * OUT_DIM], g_w2b1[OUT_DIM * OUT_DIM], g_w2b2[OUT_DIM * OUT_DIM];
// decoder weights + codebooks: fp16 h plane only
__device__ __half g_wd1h[IN_DIM * OUT_DIM];
__device__ __half g_wd2h[IN_DIM * IN_DIM];
__device__ __half g_cbh[NLEV * CB_SIZE * OUT_DIM];
__device__ float4 g_part4[4 * N_ROWS];
__device__ double g_commit;
__device__ double g_rec;

// ===================== helpers ================================================
__device__ __forceinline__ void split2h(float v, __half& h, __half& l) {
    h = __float2half_rn(v);
    l = __float2half_rn(v - __half2float(h));
}
__device__ __forceinline__ void split3b(float v, bf16& h, bf16& m, bf16& l) {
    h = __float2bfloat16_rn(v);
    float t = v - __bfloat162float(h);
    m = __float2bfloat16_rn(t);
    t -= __bfloat162float(m);
    l = __float2bfloat16_rn(t);
}
__device__ __forceinline__ uint32_t packh(__half a, __half b) {
    __half2 t = __halves2half2(a, b);
    return *reinterpret_cast<uint32_t*>(&t);
}
__device__ __forceinline__ uint32_t packb(bf16 a, bf16 b) {
    __nv_bfloat162 t = __halves2bfloat162(a, b);
    return *reinterpret_cast<uint32_t*>(&t);
}
__device__ __forceinline__ uint32_t q4c(const uint4& q, int j) {
    return j == 0 ? q.x : j == 1 ? q.y : j == 2 ? q.z : q.w;
}
#define F2U(x) __float_as_uint(x)

#define MMA16(acc, a0, a1, a2, a3, bx, by) \
    asm volatile("mma.sync.aligned.m16n8k16.row.col.f32.f16.f16.f32 " \
        "{%0,%1,%2,%3}, {%4,%5,%6,%7}, {%8,%9}, {%0,%1,%2,%3};" \
        : "+f"((acc)[0]), "+f"((acc)[1]), "+f"((acc)[2]), "+f"((acc)[3]) \
        : "r"(a0), "r"(a1), "r"(a2), "r"(a3), "r"(bx), "r"(by))

#define MMAB(acc, a0, a1, a2, a3, bx, by) \
    asm volatile("mma.sync.aligned.m16n8k16.row.col.f32.bf16.bf16.f32 " \
        "{%0,%1,%2,%3}, {%4,%5,%6,%7}, {%8,%9}, {%0,%1,%2,%3};" \
        : "+f"((acc)[0]), "+f"((acc)[1]), "+f"((acc)[2]), "+f"((acc)[3]) \
        : "r"(a0), "r"(a1), "r"(a2), "r"(a3), "r"(bx), "r"(by))

// ===================== small kernels ==========================================
// LN stats + apply + split3 to bf16 planes
__global__ void ln_kernel(const float* __restrict__ x,
                          const float* __restrict__ lng, const float* __restrict__ lnb) {
    if (blockIdx.x == 0 && threadIdx.x == 0) {
        g_commit = 0.0; g_rec = 0.0;
        for (int i = 0; i < NLEV; i++) g_cmax2[i] = 0;
    }
    int row = blockIdx.x;
    const float* xr = x + (size_t)row * IN_DIM;
    float v[3];
    float s = 0.f, s2 = 0.f;
    #pragma unroll
    for (int j = 0; j < 3; j++) {
        v[j] = xr[threadIdx.x + j * 256];
        s += v[j]; s2 += v[j] * v[j];
    }
    __shared__ float sh[16];
    __shared__ float s_mu, s_rs;
    #pragma unroll
    for (int o = 16; o; o >>= 1) {
        s  += __shfl_down_sync(0xffffffffu, s,  o);
        s2 += __shfl_down_sync(0xffffffffu, s2, o);
    }
    if ((threadIdx.x & 31) == 0) { sh[threadIdx.x >> 5] = s; sh[8 + (threadIdx.x >> 5)] = s2; }
    __syncthreads();
    if (threadIdx.x == 0) {
        float S = 0.f, S2 = 0.f;
        #pragma unroll
        for (int i = 0; i < 8; i++) { S += sh[i]; S2 += sh[8 + i]; }
        float mu = S / IN_DIM;
        float var = S2 / IN_DIM - mu * mu;
        s_mu = mu;
        s_rs = rsqrtf(var + 1e-5f);
    }
    __syncthreads();
    float mu = s_mu, rs = s_rs;
    #pragma unroll
    for (int j = 0; j < 3; j++) {
        int i = threadIdx.x + j * 256;
        float xn = (v[j] - mu) * rs * lng[i] + lnb[i];
        bf16 h, m, l;
        split3b(xn, h, m, l);
        size_t off = (size_t)row * IN_DIM + i;
        g_xn0[off] = h; g_xn1[off] = m; g_xn2[off] = l;
    }
}

__global__ void cnorm_kernel(const float* __restrict__ cb) {
    int code = blockIdx.x;
    float v = cb[(size_t)code * OUT_DIM + threadIdx.x];
    float s = v * v;
    __shared__ float sh[8];
    #pragma unroll
    for (int o = 16; o; o >>= 1) s += __shfl_down_sync(0xffffffffu, s, o);
    if ((threadIdx.x & 31) == 0) sh[threadIdx.x >> 5] = s;
    __syncthreads();
    if (threadIdx.x == 0) {
        float t = 0.f;
        #pragma unroll
        for (int i = 0; i < 8; i++) t += sh[i];
        g_cnorm[code] = t;
        atomicMax(&g_cmax2[blockIdx.x >> 10], __float_as_int(t));
    }
}

// fused prep: split3b-T W1, W2; cvt-T Wd1, Wd2 (fp16 h); cvt cb (fp16 h)
__global__ void prep_kernel(const float* __restrict__ W1, const float* __restrict__ W2,
                            const float* __restrict__ Wd1, const float* __restrict__ Wd2,
                            const float* __restrict__ cbs) {
    int b = blockIdx.x, t = threadIdx.x;
    if (b < 768) {                       // W1 [768,256] -> [256,768] split3b
        int i = b * 256 + t;
        int n = i / IN_DIM, k = i - n * IN_DIM;
        bf16 h, m, l;
        split3b(W1[(size_t)k * OUT_DIM + n], h, m, l);
        g_w1b0[i] = h; g_w1b1[i] = m; g_w1b2[i] = l;
    } else if (b < 1024) {               // W2 [256,256] split3b
        int i = (b - 768) * 256 + t;
        int n = i / OUT_DIM, k = i - n * OUT_DIM;
        bf16 h, m, l;
        split3b(W2[(size_t)k * OUT_DIM + n], h, m, l);
        g_w2b0[i] = h; g_w2b1[i] = m; g_w2b2[i] = l;
    } else if (b < 1792) {               // Wd1 [256,768] -> [768,256] cvt fp16 h
        int i = (b - 1024) * 256 + t;
        int n = i / OUT_DIM, k = i - n * OUT_DIM;
        g_wd1h[i] = __float2half_rn(Wd1[(size_t)k * IN_DIM + n]);
    } else if (b < 4096) {               // Wd2 [768,768] cvt fp16 h
        int i = (b - 1792) * 256 + t;
        int n = i / IN_DIM, k = i - n * IN_DIM;
        g_wd2h[i] = __float2half_rn(Wd2[(size_t)k * IN_DIM + n]);
    } else {                             // codebooks cvt fp16 h
        int i = (b - 4096) * 256 + t;
        g_cbh[i] = __float2half_rn(cbs[i]);
    }
}

__global__ void sum_rn2_kernel() {
    int i = (blockIdx.x * 256 + threadIdx.x) * 4;
    float4 v = *(const float4*)(g_rn2 + i);
    float s = v.x + v.y + v.z + v.w;
    __shared__ float sh[8];
    #pragma unroll
    for (int o = 16; o; o >>= 1) s += __shfl_down_sync(0xffffffffu, s, o);
    if ((threadIdx.x & 31) == 0) sh[threadIdx.x >> 5] = s;
    __syncthreads();
    if (threadIdx.x == 0) {
        float t = 0.f;
        #pragma unroll
        for (int i2 = 0; i2 < 8; i2++) t += sh[i2];
        atomicAdd(&g_commit, (double)t);
    }
}

__global__ void final_kernel(float* __restrict__ out) {
    double rec = g_rec / ((double)N_ROWS * (double)IN_DIM);
    double com = g_commit / ((double)N_ROWS * (double)OUT_DIM);
    out[0] = (float)(rec + 0.25 * com);
}

// ======= fused RQ step: resolve partials + (conditional exact rescreen) + update
__global__ void __launch_bounds__(256)
rq_step_kernel(const float* __restrict__ cb, const float* __restrict__ cn,
               float* __restrict__ out_idx, int level) {
    __shared__ float sr[256];
    __shared__ int s_idx;
    __shared__ float s_red[8];
    __shared__ float2 sw[8];
    const int row = blockIdx.x;
    const int tid = threadIdx.x;
    const int wid = tid >> 5, lane = tid & 31;

    if (tid == 0) {
        float d1 = FINF, d2 = FINF;
        int i1 = 0;
        #pragma unroll
        for (int nt = 0; nt < 4; nt++) {
            float4 p = g_part4[(size_t)nt * N_ROWS + row];
            int pi = (int)p.y;
            if (p.x < d1 || (p.x == d1 && pi < i1)) {
                d2 = fminf(d1, p.z);
                d1 = p.x; i1 = pi;
            } else {
                d2 = fminf(d2, p.x);
            }
        }
        float cm2 = __int_as_float(g_cmax2[level]);
        float E = 3e-4f * sqrtf(g_rn2[row] * cm2);
        s_idx = (d2 - d1 <= E) ? -1 : i1;   // -1 => ambiguous, exact rescreen
    }
    sr[tid] = g_res[(size_t)row * 256 + tid];
    __syncthreads();
    int idx = s_idx;

    if (idx < 0) {
        const float4* rp = (const float4*)(sr + lane * 8);
        float4 r0 = rp[0], r1 = rp[1];
        float bd = FINF; int bi = 0;
        for (int j = 0; j < 128; j++) {
            int c = wid * 128 + j;
            const float4* cp = (const float4*)(cb + (size_t)c * 256 + lane * 8);
            float4 v0 = cp[0], v1 = cp[1];
            float s = v0.x*r0.x + v0.y*r0.y + v0.z*r0.z + v0.w*r0.w
                    + v1.x*r1.x + v1.y*r1.y + v1.z*r1.z + v1.w*r1.w;
            #pragma unroll
            for (int o = 16; o; o >>= 1) s += __shfl_xor_sync(0xffffffffu, s, o);
            float d = cn[c] - 2.f * s;
            if (d < bd) { bd = d; bi = c; }
        }
        if (lane == 0) sw[wid] = make_float2(bd, (float)bi);
        __syncthreads();
        if (tid == 0) {
            float d1 = FINF; int i1 = 0;
            #pragma unroll
            for (int w = 0; w < 8; w++) {
                int wi = (int)sw[w].y;
                if (sw[w].x < d1 || (sw[w].x == d1 && wi < i1)) { d1 = sw[w].x; i1 = wi; }
            }
            s_idx = i1;
        }
        __syncthreads();
        idx = s_idx;
    }

    if (tid == 0) out_idx[(size_t)row * 4 + level] = (float)idx;

    size_t off = (size_t)row * 256 + tid;
    float r = sr[tid];
    float q = cb[(size_t)idx * 256 + tid];
    float d = r - q;
    g_res[off] = d;
    g_resh[off] = __float2half_rn(d);
    float qv = (level == 0) ? q : (g_qf[off] + q);
    g_qf[off] = qv;
    if (level == NLEV - 1) {
        __half qh, ql;
        split2h(qv, qh, ql);
        g_qfh[off] = qh; g_qfl[off] = ql;
    }
    float cs = d * d;
    #pragma unroll
    for (int o = 16; o; o >>= 1) cs += __shfl_down_sync(0xffffffffu, cs, o);
    if ((tid & 31) == 0) s_red[tid >> 5] = cs;
    __syncthreads();
    if (tid == 0) {
        float t = 0.f;
        #pragma unroll
        for (int i = 0; i < 8; i++) t += s_red[i];
        g_rn2[row] = t;
    }
}

// ===================== bf16 6-term GEMM (encoder), BK=16, double-buffered =====
// Block 128x256, 8 warps (2M x 4N), warp 64x64. A and B pre-split: 3 bf16 planes.
// Terms: hh, hm, mh, hl, lh, mm  (error ~2^-24 => fp32-grade; feeds argmin).
// Pipeline: prefetch LDG(c+1) -> MMA(c) -> STS(c+1 -> other stage) -> sync.
// EPI: 4 = res fp32 + resh fp16 + per-row rn2 (enc2)
//      5 = relu -> h1 as 3 bf16 planes (enc1)
#define B_APL 2048
#define B_BBASE 6144
#define B_BPL 4096
#define B_STG 18432
#define SMEM_BB (2 * B_STG * 2)   // 73728 bytes

template <int EPI>
__global__ void __launch_bounds__(256, 1)
gemm_b(const bf16* __restrict__ A0, const bf16* __restrict__ A1, const bf16* __restrict__ A2,
       const bf16* __restrict__ B0, const bf16* __restrict__ B1, const bf16* __restrict__ B2,
       const float* __restrict__ bias, float* __restrict__ C,
       bf16* __restrict__ D0, bf16* __restrict__ D1, bf16* __restrict__ D2,
       int K, int Nn)
{
    extern __shared__ bf16 smb[];
    const int tid = threadIdx.x;
    const int lane = tid & 31;
    const int wid = tid >> 5;
    const int wm = wid >> 2;
    const int wn = wid & 3;
    const int r = lane >> 2;
    const int cq = lane & 3;
    const int m0 = blockIdx.y * 128;
    const int n0 = blockIdx.x * 256;

    const bf16* Ap[3] = {A0, A1, A2};
    const bf16* Bp[3] = {B0, B1, B2};

    float acc[4][8][4];
    #pragma unroll
    for (int mt = 0; mt < 4; mt++)
        #pragma unroll
        for (int nt = 0; nt < 8; nt++)
            #pragma unroll
            for (int q = 0; q < 4; q++) acc[mt][nt][q] = 0.f;

    const int NC = K >> 4;
    // prefetch units: A = 3 planes x 128 rows x 2 halves = 768; B = 3x256x2 = 1536
    uint4 afu[3], bfu[6];

    auto prefetch = [&](int c) {
        const int k0 = c * 16;
        #pragma unroll
        for (int i = 0; i < 3; i++) {
            int u = tid + i * 256;
            int s = u >> 8, rem = u & 255;
            int row = rem >> 1, h = rem & 1;
            afu[i] = *(const uint4*)(Ap[s] + (size_t)(m0 + row) * K + k0 + h * 8);
        }
        #pragma unroll
        for (int i = 0; i < 6; i++) {
            int u = tid + i * 256;
            int s = u / 512, rem = u % 512;
            int row = rem >> 1, h = rem & 1;
            bfu[i] = *(const uint4*)(Bp[s] + (size_t)(n0 + row) * K + k0 + h * 8);
        }
    };
    auto store_stage = [&](int stg) {
        bf16* st = smb + stg * B_STG;
        #pragma unroll
        for (int i = 0; i < 3; i++) {
            int u = tid + i * 256;
            int s = u >> 8, rem = u & 255;
            int row = rem >> 1, h = rem & 1;
            bf16* base = st + s * B_APL + row * 16;
            #pragma unroll
            for (int j = 0; j < 4; j++) {
                int ps = (j + (row >> 2)) & 3;
                *(uint32_t*)(base + ps * 4 + h * 2) = q4c(afu[i], j);
            }
        }
        #pragma unroll
        for (int i = 0; i < 6; i++) {
            int u = tid + i * 256;
            int s = u / 512, rem = u % 512;
            int row = rem >> 1, h = rem & 1;
            bf16* base = st + B_BBASE + s * B_BPL + row * 16;
            #pragma unroll
            for (int j = 0; j < 4; j++) {
                int ps = (j + (row >> 2)) & 3;
                *(uint32_t*)(base + ps * 4 + h * 2) = q4c(bfu[i], j);
            }
        }
    };

    prefetch(0);
    store_stage(0);
    __syncthreads();

    const int TA[6] = {0, 0, 1, 0, 2, 1};
    const int TB[6] = {0, 1, 0, 2, 0, 1};

    for (int c = 0; c < NC; c++) {
        if (c + 1 < NC) prefetch(c + 1);

        const bf16* st = smb + (c & 1) * B_STG;
        uint2 fbr[3][8];
        #pragma unroll
        for (int s = 0; s < 3; s++)
            #pragma unroll
            for (int nt = 0; nt < 8; nt++) {
                int n = wn * 64 + nt * 8 + r;
                int ps = (cq + (n >> 2)) & 3;
                fbr[s][nt] = *(const uint2*)(st + B_BBASE + s * B_BPL + n * 16 + ps * 4);
            }
        #pragma unroll
        for (int mt = 0; mt < 4; mt++) {
            int row = wm * 64 + mt * 16 + r;
            int ps  = (cq + (row >> 2)) & 3;
            int ps8 = (cq + (row >> 2) + 2) & 3;
            uint2 ua[3], va[3];
            #pragma unroll
            for (int s = 0; s < 3; s++) {
                ua[s] = *(const uint2*)(st + s * B_APL + row * 16 + ps * 4);
                va[s] = *(const uint2*)(st + s * B_APL + (row + 8) * 16 + ps8 * 4);
            }
            #pragma unroll
            for (int t = 0; t < 6; t++) {
                int sa = TA[t], sb = TB[t];
                #pragma unroll
                for (int nt = 0; nt < 8; nt++)
                    MMAB(acc[mt][nt], ua[sa].x, va[sa].x, ua[sa].y, va[sa].y,
                         fbr[sb][nt].x, fbr[sb][nt].y);
            }
        }

        if (c + 1 < NC) store_stage((c + 1) & 1);
        __syncthreads();
    }

    // =================== epilogue ===================
    if (EPI == 5) {
        // relu(acc+bias) -> 3 bf16 planes (h1 for enc2, fp32-grade via split3b)
        #pragma unroll
        for (int mt = 0; mt < 4; mt++) {
            int row = m0 + wm * 64 + mt * 16 + r;
            #pragma unroll
            for (int nt = 0; nt < 8; nt++) {
                int col = n0 + wn * 64 + nt * 8 + 2 * cq;
                float2 bb = *(const float2*)(bias + col);
                float o[4];
                o[0] = fmaxf(acc[mt][nt][0] + bb.x, 0.f);
                o[1] = fmaxf(acc[mt][nt][1] + bb.y, 0.f);
                o[2] = fmaxf(acc[mt][nt][2] + bb.x, 0.f);
                o[3] = fmaxf(acc[mt][nt][3] + bb.y, 0.f);
                bf16 h[4], m[4], l[4];
                #pragma unroll
                for (int e = 0; e < 4; e++) split3b(o[e], h[e], m[e], l[e]);
                size_t o0 = (size_t)row * Nn + col;
                size_t o1 = (size_t)(row + 8) * Nn + col;
                *(uint32_t*)(D0 + o0) = packb(h[0], h[1]);
                *(uint32_t*)(D1 + o0) = packb(m[0], m[1]);
                *(uint32_t*)(D2 + o0) = packb(l[0], l[1]);
                *(uint32_t*)(D0 + o1) = packb(h[2], h[3]);
                *(uint32_t*)(D1 + o1) = packb(m[2], m[3]);
                *(uint32_t*)(D2 + o1) = packb(l[2], l[3]);
            }
        }
    } else {
        // EPI 4 (enc2): res fp32 + resh fp16 plane + per-row rn2
        float lsr[4][2];
        #pragma unroll
        for (int mt = 0; mt < 4; mt++) { lsr[mt][0] = 0.f; lsr[mt][1] = 0.f; }
        #pragma unroll
        for (int mt = 0; mt < 4; mt++) {
            int row = m0 + wm * 64 + mt * 16 + r;
            #pragma unroll
            for (int nt = 0; nt < 8; nt++) {
                int col = n0 + wn * 64 + nt * 8 + 2 * cq;
                float2 bb = *(const float2*)(bias + col);
                float o0 = acc[mt][nt][0] + bb.x, o1 = acc[mt][nt][1] + bb.y;
                float o2 = acc[mt][nt][2] + bb.x, o3 = acc[mt][nt][3] + bb.y;
                *(float2*)(C + (size_t)row * Nn + col) = make_float2(o0, o1);
                *(float2*)(C + (size_t)(row + 8) * Nn + col) = make_float2(o2, o3);
                *(uint32_t*)(g_resh + (size_t)row * Nn + col) =
                    packh(__float2half_rn(o0), __float2half_rn(o1));
                *(uint32_t*)(g_resh + (size_t)(row + 8) * Nn + col) =
                    packh(__float2half_rn(o2), __float2half_rn(o3));
                lsr[mt][0] = fmaf(o0, o0, fmaf(o1, o1, lsr[mt][0]));
                lsr[mt][1] = fmaf(o2, o2, fmaf(o3, o3, lsr[mt][1]));
            }
        }
        __syncthreads();
        float* sred = (float*)smb;   // [128][4]
        #pragma unroll
        for (int mt = 0; mt < 4; mt++) {
            float s0 = lsr[mt][0], s1 = lsr[mt][1];
            s0 += __shfl_xor_sync(0xffffffffu, s0, 1);
            s0 += __shfl_xor_sync(0xffffffffu, s0, 2);
            s1 += __shfl_xor_sync(0xffffffffu, s1, 1);
            s1 += __shfl_xor_sync(0xffffffffu, s1, 2);
            if (cq == 0) {
                int lr = wm * 64 + mt * 16 + r;
                sred[lr * 4 + wn] = s0;
                sred[(lr + 8) * 4 + wn] = s1;
            }
        }
        __syncthreads();
        if (tid < 128)
            g_rn2[m0 + tid] = sred[tid * 4] + sred[tid * 4 + 1]
                            + sred[tid * 4 + 2] + sred[tid * 4 + 3];
    }
}

// ===================== fp16 k16 NTERM GEMM, presplit operands (from R8) =======
template <int EPI, int NTERM>
__global__ void __launch_bounds__(256, 1)
gemm_h(const __half* __restrict__ A0, const __half* __restrict__ A1,
       const __half* __restrict__ B0,
       const float* __restrict__ bias, float* __restrict__ C,
       __half* __restrict__ C0, __half* __restrict__ C1,
       int K, int Nn,
       const float* __restrict__ xref, float4* __restrict__ part)
{
    constexpr int PA = (NTERM >= 2) ? 2 : 1;
    constexpr int APL = 2048;
    constexpr int BPL = 4096;
    constexpr int BBASE = PA * 2 * APL;
    constexpr int STG = PA * 2 * APL + 2 * BPL;

    extern __shared__ __half smh[];
    const int tid = threadIdx.x;
    const int lane = tid & 31;
    const int wid = tid >> 5;
    const int wm = wid >> 2;
    const int wn = wid & 3;
    const int r = lane >> 2;
    const int cq = lane & 3;
    const int m0 = blockIdx.y * 128;
    const int n0 = blockIdx.x * 256;

    const int srow = tid >> 1;
    const int sb   = tid & 1;
    const __half* Ap[2] = {A0, A1};

    float acc[4][8][4];
    #pragma unroll
    for (int mt = 0; mt < 4; mt++)
        #pragma unroll
        for (int nt = 0; nt < 8; nt++)
            #pragma unroll
            for (int q = 0; q < 4; q++) acc[mt][nt][q] = 0.f;

    const int NC = K >> 5;
    uint4 af[PA][2];
    uint4 bf[4];

    auto load_regs = [&](int c) {
        #pragma unroll
        for (int s = 0; s < PA; s++) {
            const uint4* ap = (const uint4*)(Ap[s] + (size_t)(m0 + srow) * K + c * 32 + sb * 16);
            af[s][0] = ap[0];
            af[s][1] = ap[1];
        }
        const uint4* bp = (const uint4*)(B0 + (size_t)(n0 + tid) * K + c * 32);
        bf[0] = bp[0]; bf[1] = bp[1]; bf[2] = bp[2]; bf[3] = bp[3];
    };
    auto store_stage = [&](int stg) {
        __half* st = smh + stg * STG;
        #pragma unroll
        for (int s = 0; s < PA; s++) {
            __half* base = st + (s * 2 + sb) * APL + srow * 16;
            #pragma unroll
            for (int j = 0; j < 4; j++) {
                int jj = (j + 2 * sb) & 3;
                int ps = (jj + (srow >> 2)) & 3;
                uint2 val;
                val.x = q4c(af[s][0], jj);
                val.y = q4c(af[s][1], jj);
                *(uint2*)(base + ps * 4) = val;
            }
        }
        #pragma unroll
        for (int b = 0; b < 2; b++) {
            __half* bbase = st + BBASE + b * BPL + tid * 16;
            #pragma unroll
            for (int j = 0; j < 4; j++) {
                int jj = (j + 2 * b) & 3;
                int ps = (jj + (tid >> 2)) & 3;
                uint2 val;
                val.x = q4c(bf[2 * b], jj);
                val.y = q4c(bf[2 * b + 1], jj);
                *(uint2*)(bbase + ps * 4) = val;
            }
        }
    };

    load_regs(0);
    store_stage(0);
    __syncthreads();

    for (int c = 0; c < NC; c++) {
        if (c + 1 < NC) load_regs(c + 1);

        const __half* st = smh + (c & 1) * STG;
        #pragma unroll
        for (int b = 0; b < 2; b++) {
            uint2 fbr[8];
            #pragma unroll
            for (int nt = 0; nt < 8; nt++) {
                int n = wn * 64 + nt * 8 + r;
                int ps = (cq + (n >> 2)) & 3;
                fbr[nt] = *(const uint2*)(st + BBASE + b * BPL + n * 16 + ps * 4);
            }
            #pragma unroll
            for (int mt = 0; mt < 4; mt++) {
                int row = wm * 64 + mt * 16 + r;
                int ps  = (cq + (row >> 2)) & 3;
                int ps8 = (cq + (row >> 2) + 2) & 3;
                uint2 ua[PA], va[PA];
                #pragma unroll
                for (int s = 0; s < PA; s++) {
                    ua[s] = *(const uint2*)(st + (s * 2 + b) * APL + row * 16 + ps * 4);
                    va[s] = *(const uint2*)(st + (s * 2 + b) * APL + (row + 8) * 16 + ps8 * 4);
                }
                #pragma unroll
                for (int t = 0; t < NTERM; t++) {
                    #pragma unroll
                    for (int nt = 0; nt < 8; nt++)
                        MMA16(acc[mt][nt], ua[t].x, va[t].x, ua[t].y, va[t].y,
                              fbr[nt].x, fbr[nt].y);
                }
            }
        }

        if (c + 1 < NC) store_stage((c + 1) & 1);
        __syncthreads();
    }

    // =================== epilogue ===================
    if (EPI == 1) {
        #pragma unroll
        for (int mt = 0; mt < 4; mt++) {
            int row = m0 + wm * 64 + mt * 16 + r;
            #pragma unroll
            for (int nt = 0; nt < 8; nt++) {
                int col = n0 + wn * 64 + nt * 8 + 2 * cq;
                float2 bb = *(const float2*)(bias + col);
                float o0 = fmaxf(acc[mt][nt][0] + bb.x, 0.f);
                float o1 = fmaxf(acc[mt][nt][1] + bb.y, 0.f);
                float o2 = fmaxf(acc[mt][nt][2] + bb.x, 0.f);
                float o3 = fmaxf(acc[mt][nt][3] + bb.y, 0.f);
                __half h0, l0, h1, l1, h2, l2, h3, l3;
                split2h(o0, h0, l0); split2h(o1, h1, l1);
                split2h(o2, h2, l2); split2h(o3, h3, l3);
                *(uint32_t*)(C0 + (size_t)row * Nn + col) = packh(h0, h1);
                *(uint32_t*)(C1 + (size_t)row * Nn + col) = packh(l0, l1);
                *(uint32_t*)(C0 + (size_t)(row + 8) * Nn + col) = packh(h2, h3);
                *(uint32_t*)(C1 + (size_t)(row + 8) * Nn + col) = packh(l2, l3);
            }
        }
    } else if (EPI == 2) {
        float lsum = 0.f;
        #pragma unroll
        for (int mt = 0; mt < 4; mt++) {
            int row = m0 + wm * 64 + mt * 16 + r;
            #pragma unroll
            for (int nt = 0; nt < 8; nt++) {
                int col = n0 + wn * 64 + nt * 8 + 2 * cq;
                float2 bb = *(const float2*)(bias + col);
                float2 x0 = *(const float2*)(xref + (size_t)row * Nn + col);
                float2 x1 = *(const float2*)(xref + (size_t)(row + 8) * Nn + col);
                float o0 = acc[mt][nt][0] + bb.x, o1 = acc[mt][nt][1] + bb.y;
                float o2 = acc[mt][nt][2] + bb.x, o3 = acc[mt][nt][3] + bb.y;
                float d0 = o0 - x0.x, d1 = o1 - x0.y, d2 = o2 - x1.x, d3 = o3 - x1.y;
                lsum = fmaf(d0, d0, lsum); lsum = fmaf(d1, d1, lsum);
                lsum = fmaf(d2, d2, lsum); lsum = fmaf(d3, d3, lsum);
                float* c0 = C + (size_t)row * Nn + col;        // 4B-aligned only
                float* c1 = C + (size_t)(row + 8) * Nn + col;
                c0[0] = o0; c0[1] = o1; c1[0] = o2; c1[1] = o3;
            }
        }
        #pragma unroll
        for (int o = 16; o; o >>= 1) lsum += __shfl_down_sync(0xffffffffu, lsum, o);
        if (lane == 0) atomicAdd(&g_rec, (double)lsum);
    } else {  // EPI 3: top-2 distance partial (bias = cnorm)
        __syncthreads();
        float4* sred = (float4*)smh;
        #pragma unroll
        for (int mt = 0; mt < 4; mt++) {
            float bd[2] = {FINF, FINF}, b2[2] = {FINF, FINF};
            int bi[2] = {0, 0};
            #pragma unroll
            for (int nt = 0; nt < 8; nt++) {
                int col = n0 + wn * 64 + nt * 8 + 2 * cq;
                float2 cn = *(const float2*)(bias + col);
                float dv[4];
                dv[0] = cn.x - 2.f * acc[mt][nt][0];
                dv[1] = cn.y - 2.f * acc[mt][nt][1];
                dv[2] = cn.x - 2.f * acc[mt][nt][2];
                dv[3] = cn.y - 2.f * acc[mt][nt][3];
                #pragma unroll
                for (int e = 0; e < 4; e++) {
                    int slot = e >> 1;
                    int ci = col + (e & 1);
                    if (dv[e] < bd[slot]) { b2[slot] = bd[slot]; bd[slot] = dv[e]; bi[slot] = ci; }
                    else b2[slot] = fminf(b2[slot], dv[e]);
                }
            }
            #pragma unroll
            for (int off = 1; off <= 2; off <<= 1) {
                #pragma unroll
                for (int slot = 0; slot < 2; slot++) {
                    float od = __shfl_xor_sync(0xffffffffu, bd[slot], off);
                    int   oi = __shfl_xor_sync(0xffffffffu, bi[slot], off);
                    float o2 = __shfl_xor_sync(0xffffffffu, b2[slot], off);
                    if (od < bd[slot] || (od == bd[slot] && oi < bi[slot])) {
                        b2[slot] = fminf(bd[slot], o2);
                        bd[slot] = od; bi[slot] = oi;
                    } else {
                        b2[slot] = fminf(b2[slot], od);
                    }
                }
            }
            if (cq == 0) {
                int lr = wm * 64 + mt * 16 + r;
                sred[lr * 4 + wn] = make_float4(bd[0], (float)bi[0], b2[0], 0.f);
                sred[(lr + 8) * 4 + wn] = make_float4(bd[1], (float)bi[1], b2[1], 0.f);
            }
        }
        __syncthreads();
        if (tid < 128) {
            float d1 = FINF, d2 = FINF;
            int i1 = 0;
            #pragma unroll
            for (int w = 0; w < 4; w++) {
                float4 p = sred[tid * 4 + w];
                int pi = (int)p.y;
                if (p.x < d1 || (p.x == d1 && pi < i1)) {
                    d2 = fminf(d1, p.z);
                    d1 = p.x; i1 = pi;
                } else {
                    d2 = fminf(d2, p.x);
                }
            }
            part[(size_t)blockIdx.x * N_ROWS + m0 + tid] =
                make_float4(d1, (float)i1, d2, 0.f);
        }
    }
}

// ===================== launch ==================================================
extern "C" void kernel_launch(void* const* d_in, const int* in_sizes, int n_in,
                              void* d_out, int out_size)
{
    (void)in_sizes; (void)n_in; (void)out_size;
    const float* x    = (const float*)d_in[0];
    const float* ln_g = (const float*)d_in[1];
    const float* ln_b = (const float*)d_in[2];
    const float* W1   = (const float*)d_in[3];
    const float* b1   = (const float*)d_in[4];
    const float* W2   = (const float*)d_in[5];
    const float* b2   = (const float*)d_in[6];
    const float* Wd1  = (const float*)d_in[7];
    const float* bd1  = (const float*)d_in[8];
    const float* Wd2  = (const float*)d_in[9];
    const float* bd2  = (const float*)d_in[10];
    const float* cbs  = (const float*)d_in[11];

    float* out   = (float*)d_out;
    float* recon = out + 1;
    float* oidx  = out + 1 + (size_t)N_ROWS * IN_DIM;

    void* p;
    cudaGetSymbolAddress(&p, g_res);   float* res   = (float*)p;
    cudaGetSymbolAddress(&p, g_cnorm); float* cnrm  = (float*)p;
    cudaGetSymbolAddress(&p, g_resh);  __half* resh = (__half*)p;
    cudaGetSymbolAddress(&p, g_qfh);   __half* qfh  = (__half*)p;
    cudaGetSymbolAddress(&p, g_qfl);   __half* qfl  = (__half*)p;
    cudaGetSymbolAddress(&p, g_hdh);   __half* hdh  = (__half*)p;
    cudaGetSymbolAddress(&p, g_hdl);   __half* hdl  = (__half*)p;
    cudaGetSymbolAddress(&p, g_xn0);   bf16* xn0    = (bf16*)p;
    cudaGetSymbolAddress(&p, g_xn1);   bf16* xn1    = (bf16*)p;
    cudaGetSymbolAddress(&p, g_xn2);   bf16* xn2    = (bf16*)p;
    cudaGetSymbolAddress(&p, g_h1b0);  bf16* h1b0   = (bf16*)p;
    cudaGetSymbolAddress(&p, g_h1b1);  bf16* h1b1   = (bf16*)p;
    cudaGetSymbolAddress(&p, g_h1b2);  bf16* h1b2   = (bf16*)p;
    cudaGetSymbolAddress(&p, g_w1b0);  bf16* w1b0   = (bf16*)p;
    cudaGetSymbolAddress(&p, g_w1b1);  bf16* w1b1   = (bf16*)p;
    cudaGetSymbolAddress(&p, g_w1b2);  bf16* w1b2   = (bf16*)p;
    cudaGetSymbolAddress(&p, g_w2b0);  bf16* w2b0   = (bf16*)p;
    cudaGetSymbolAddress(&p, g_w2b1);  bf16* w2b1   = (bf16*)p;
    cudaGetSymbolAddress(&p, g_w2b2);  bf16* w2b2   = (bf16*)p;
    cudaGetSymbolAddress(&p, g_wd1h);  __half* wd1h = (__half*)p;
    cudaGetSymbolAddress(&p, g_wd2h);  __half* wd2h = (__half*)p;
    cudaGetSymbolAddress(&p, g_cbh);   __half* cbh  = (__half*)p;
    cudaGetSymbolAddress(&p, g_part4); float4* part = (float4*)p;

    const int HS1 = 2 * (1 * 4096 + 8192) * 2;        // NTERM=1: 49152
    const int HS2 = 2 * (2 * 4096 + 8192) * 2;        // NTERM=2: 65536
    cudaFuncSetAttribute(gemm_b<5>, cudaFuncAttributeMaxDynamicSharedMemorySize, SMEM_BB);
    cudaFuncSetAttribute(gemm_b<4>, cudaFuncAttributeMaxDynamicSharedMemorySize, SMEM_BB);
    cudaFuncSetAttribute(gemm_h<3, 1>, cudaFuncAttributeMaxDynamicSharedMemorySize, HS1);
    cudaFuncSetAttribute(gemm_h<1, 2>, cudaFuncAttributeMaxDynamicSharedMemorySize, HS2);
    cudaFuncSetAttribute(gemm_h<2, 2>, cudaFuncAttributeMaxDynamicSharedMemorySize, HS2);

    prep_kernel<<<8192, 256>>>(W1, W2, Wd1, Wd2, cbs);
    ln_kernel<<<N_ROWS, 256>>>(x, ln_g, ln_b);

    // encoder (bf16 6-term, fp32-grade: feeds argmin)
    gemm_b<5><<<dim3(1, N_ROWS / 128), 256, SMEM_BB>>>(
        xn0, xn1, xn2, w1b0, w1b1, w1b2, b1,
        nullptr, h1b0, h1b1, h1b2, IN_DIM, OUT_DIM);
    gemm_b<4><<<dim3(1, N_ROWS / 128), 256, SMEM_BB>>>(
        h1b0, h1b1, h1b2, w2b0, w2b1, w2b2, b2,
        res, nullptr, nullptr, nullptr, OUT_DIM, OUT_DIM);
    cnorm_kernel<<<NLEV * CB_SIZE, 256>>>(cbs);

    // residual quantization: 1-term fp16 prescreen + margin-certified rescreen
    for (int l = 0; l < NLEV; l++) {
        gemm_h<3, 1><<<dim3(4, N_ROWS / 128), 256, HS1>>>(
            resh, nullptr, cbh + (size_t)l * CB_SIZE * OUT_DIM,
            cnrm + l * CB_SIZE, nullptr, nullptr, nullptr,
            OUT_DIM, CB_SIZE, nullptr, part);
        rq_step_kernel<<<N_ROWS, 256>>>(cbs + (size_t)l * CB_SIZE * OUT_DIM,
                                        cnrm + l * CB_SIZE, oidx, l);
        sum_rn2_kernel<<<64, 256>>>();
    }

    // decoder (2-term: exact-A x fp16-B)
    gemm_h<1, 2><<<dim3(3, N_ROWS / 128), 256, HS2>>>(
        qfh, qfl, wd1h, bd1, nullptr, hdh, hdl,
        OUT_DIM, IN_DIM, nullptr, nullptr);
    gemm_h<2, 2><<<dim3(3, N_ROWS / 128), 256, HS2>>>(
        hdh, hdl, wd2h, bd2, recon, nullptr, nullptr,
        IN_DIM, IN_DIM, x, nullptr);

    final_kernel<<<1, 1>>>(out);
}